// round 10
// baseline (speedup 1.0000x reference)
#include <cuda_runtime.h>

#define NB 16
#define PN 32
#define PS 128
#define NH 8
#define NE 64
// out: [NB, 4096, NH, NE] fp32; out[b,l,h,e] = Vintra[b,l/32,h,e] + Vinter[b,l/128,h,e]

typedef unsigned long long ull;

__device__ float g_Vinter[NB * PN * NH * NE];   // 1 MB, normalized
__device__ int g_flag[128];                     // inter-done flags, zero-init

// Packed f32x2 ops — operands stay in aligned register pairs.
__device__ __forceinline__ ull fma2(ull a, ull b, ull c) {
    ull d; asm("fma.rn.f32x2 %0, %1, %2, %3;" : "=l"(d) : "l"(a), "l"(b), "l"(c)); return d;
}
__device__ __forceinline__ ull mul2(ull a, ull b) {
    ull d; asm("mul.rn.f32x2 %0, %1, %2;" : "=l"(d) : "l"(a), "l"(b)); return d;
}
__device__ __forceinline__ ull add2(ull a, ull b) {
    ull d; asm("add.rn.f32x2 %0, %1, %2;" : "=l"(d) : "l"(a), "l"(b)); return d;
}
__device__ __forceinline__ ull pack2(float lo, float hi) {
    ull r; asm("mov.b64 %0, {%1, %2};" : "=l"(r) : "f"(lo), "f"(hi)); return r;
}
__device__ __forceinline__ float2 unpack2(ull v) {
    float2 f; asm("mov.b64 {%0, %1}, %2;" : "=f"(f.x), "=f"(f.y) : "l"(v)); return f;
}

// ---- dynamic smem layout (float offsets), intra path (round-5 proven) ----
// K^T and V stored PRE-DUPLICATED ({x,x} pairs): inner loops are pure
// LDS.128 -> fma.rn.f32x2, no register pack MOVs.
#define OQT   0        // Q^T      [64e][128q]          8192 floats
#define OKT   8192     // K^T dup  [64e][128(2k)]       8192
#define OV    16384    // V dup    [64k][128(2e)]       8192
#define OS    24576    // S^T [64k][SPAD]=8448; also bounce temp
#define OSUM  33024    // intra ssum [128]
#define SMEMF 33152    // 132608 bytes -> 1 CTA/SM
#define SPAD  132

extern __shared__ float smf[];

// ONE kernel, grid = 256 x 256 threads, 1 CTA/SM:
//   blk < 128:  inter (b,h)=blk: 32q x 32k over 256 threads -> g_Vinter,
//               then __threadfence + flag. All wave-1 resident (256 blks,
//               148 slots, blocks 0..147 first) -> no deadlock.
//   blk >= 128: intra (b,h)=blk-128: 128q x 128k two-phase GEMM (round-5),
//               then spin on flag (long since set) and write the FINAL
//               broadcast output rows directly (fused bcast).
// Single-pass softmax without max-subtraction: scores q.k/8 with unit-normal
// inputs are bounded (|s| < ~7) so exp cannot overflow; mathematically
// identical to reference softmax up to fp32 add order.
__global__ __launch_bounds__(256) void attn_kernel(
    const float* __restrict__ q_inter, const float* __restrict__ k_inter,
    const float* __restrict__ v_inter,
    const float* __restrict__ q_intra, const float* __restrict__ k_intra,
    const float* __restrict__ v_intra,
    float* __restrict__ out)
{
    const int blk = blockIdx.x;
    const int t = threadIdx.x;

    if (blk < 128) {
        // ================= inter: 32q x 32k, all 256 threads =================
        const int bh = blk;
        const int b = bh >> 3, h = bh & 7;

        // stage K(0), V(2048), Q(4096); scores at 6144 [32][33]
        {
            const float4* k4 = (const float4*)k_inter;
            const float4* v4 = (const float4*)v_inter;
            const float4* q4 = (const float4*)q_inter;
#pragma unroll
            for (int i = 0; i < 2; i++) {
                int idx = t + i * 256;             // 32 rows x 16 float4
                int j = idx >> 4, e4 = idx & 15;
                int src = ((b * PN + j) * NH + h) * 16 + e4;
                *(float4*)(smf + idx * 4) = k4[src];
                *(float4*)(smf + 2048 + idx * 4) = v4[src];
                float4 qv = q4[src];
                *(float4*)(smf + 4096 + idx * 4) =
                    make_float4(qv.x * 0.125f, qv.y * 0.125f, qv.z * 0.125f, qv.w * 0.125f);
            }
        }
        __syncthreads();

        const int qi = t >> 3;       // 0..31
        {
            // phase A: thread (qi, kg) -> scores for keys 4*kg..4*kg+3
            const int kg = t & 7;
            const ulonglong2* qp = (const ulonglong2*)(smf + 4096) + qi * 16;
            const ulonglong2* kp = (const ulonglong2*)(smf) + kg * 64;
            ull a0 = 0, a1 = 0, a2 = 0, a3 = 0;
#pragma unroll
            for (int i = 0; i < 16; i++) {
                ulonglong2 qd = qp[i];
                ulonglong2 k0 = kp[i];
                ulonglong2 k1 = kp[16 + i];
                ulonglong2 k2 = kp[32 + i];
                ulonglong2 k3 = kp[48 + i];
                a0 = fma2(qd.x, k0.x, a0); a0 = fma2(qd.y, k0.y, a0);
                a1 = fma2(qd.x, k1.x, a1); a1 = fma2(qd.y, k1.y, a1);
                a2 = fma2(qd.x, k2.x, a2); a2 = fma2(qd.y, k2.y, a2);
                a3 = fma2(qd.x, k3.x, a3); a3 = fma2(qd.y, k3.y, a3);
            }
            float2 f0 = unpack2(a0), f1 = unpack2(a1), f2 = unpack2(a2), f3 = unpack2(a3);
            smf[6144 + (4 * kg + 0) * 33 + qi] = __expf(f0.x + f0.y);
            smf[6144 + (4 * kg + 1) * 33 + qi] = __expf(f1.x + f1.y);
            smf[6144 + (4 * kg + 2) * 33 + qi] = __expf(f2.x + f2.y);
            smf[6144 + (4 * kg + 3) * 33 + qi] = __expf(f3.x + f3.y);
        }
        __syncthreads();
        {
            // phase B: thread (qi, eg) -> 8 elems eg*8..+7, normalized
            const int eg = t & 7;
            const ulonglong2* vbase = (const ulonglong2*)(smf + 2048);
            ull ob0 = 0, ob1 = 0, ob2 = 0, ob3 = 0;
            float ss = 0.f;
#pragma unroll 8
            for (int k = 0; k < PN; k++) {
                float s = smf[6144 + k * 33 + qi];
                ss += s;
                ull sp = pack2(s, s);
                ulonglong2 v0 = vbase[k * 16 + 2 * eg];
                ulonglong2 v1 = vbase[k * 16 + 2 * eg + 1];
                ob0 = fma2(sp, v0.x, ob0);
                ob1 = fma2(sp, v0.y, ob1);
                ob2 = fma2(sp, v1.x, ob2);
                ob3 = fma2(sp, v1.y, ob3);
            }
            float iv = 1.0f / ss;
            ull ip = pack2(iv, iv);
            float2 g0 = unpack2(mul2(ob0, ip));
            float2 g1 = unpack2(mul2(ob1, ip));
            float2 g2 = unpack2(mul2(ob2, ip));
            float2 g3 = unpack2(mul2(ob3, ip));
            float* dst = g_Vinter + ((size_t)(b * PN + qi) * NH + h) * NE + eg * 8;
            *(float4*)(dst)     = make_float4(g0.x, g0.y, g1.x, g1.y);
            *(float4*)(dst + 4) = make_float4(g2.x, g2.y, g3.x, g3.y);
        }
        __syncthreads();
        if (t == 0) {
            __threadfence();                 // release g_Vinter writes
            atomicExch(&g_flag[bh], 1);
        }
    } else {
        // ================= intra: 128q x 128k (round-5 structure) =================
        const int bh = blk - 128;
        const int b = bh >> 3, h = bh & 7;

        // ---- build Q^T (pre-scaled by 1/8) via smem bounce ----
        float* tempQ = smf + OS;   // [128][65]
        {
            const float4* q4 = (const float4*)q_intra;
#pragma unroll
            for (int i = 0; i < 8; i++) {
                int idx = t + i * 256;
                int q = idx >> 4, e4 = idx & 15;
                float4 v = q4[((b * PS + q) * NH + h) * 16 + e4];
                float* d = tempQ + q * 65 + 4 * e4;
                d[0] = v.x * 0.125f; d[1] = v.y * 0.125f;
                d[2] = v.z * 0.125f; d[3] = v.w * 0.125f;
            }
        }
        __syncthreads();
#pragma unroll
        for (int i = 0; i < 8; i++) {
            int idx = t + i * 256;
            int e = idx >> 5, q0 = (idx & 31) * 4;
            float4 w;
            w.x = tempQ[(q0 + 0) * 65 + e];
            w.y = tempQ[(q0 + 1) * 65 + e];
            w.z = tempQ[(q0 + 2) * 65 + e];
            w.w = tempQ[(q0 + 3) * 65 + e];
            *(float4*)(smf + OQT + e * 128 + q0) = w;
        }
        __syncthreads();

        const int qg = t >> 4;         // 0..15
        const int kgA = t & 15;        // phase A key group (4 keys)
        const int egB = t & 15;        // phase B e group (4 elems)
        const int q0 = qg * 8;

        ull o[4][4];                   // packed along q
        ull sa[4];
#pragma unroll
        for (int a = 0; a < 4; a++) {
            sa[a] = 0ull;
#pragma unroll
            for (int j = 0; j < 4; j++) o[a][j] = 0ull;
        }

        for (int c = 0; c < 2; c++) {
            // ---- stage: K -> bounce tempK; V -> duplicated pairs ----
            float* tempK = smf + OS;   // [64][65]
            {
                const float4* k4 = (const float4*)k_intra;
                const float4* v4 = (const float4*)v_intra;
#pragma unroll
                for (int i = 0; i < 4; i++) {
                    int idx = t + i * 256;
                    int k = idx >> 4, e4 = idx & 15;
                    int src = ((b * PS + c * 64 + k) * NH + h) * 16 + e4;
                    float4 kv = k4[src];
                    float* d = tempK + k * 65 + 4 * e4;
                    d[0] = kv.x; d[1] = kv.y; d[2] = kv.z; d[3] = kv.w;
                    float4 vv = v4[src];
                    *(float4*)(smf + OV + k * 128 + 8 * e4)     = make_float4(vv.x, vv.x, vv.y, vv.y);
                    *(float4*)(smf + OV + k * 128 + 8 * e4 + 4) = make_float4(vv.z, vv.z, vv.w, vv.w);
                }
            }
            __syncthreads();
            // ---- K^T duplicated transpose: [e][2k] pairs {k,k} ----
#pragma unroll
            for (int i = 0; i < 8; i++) {
                int idx = t + i * 256;
                int e = idx >> 5, kh = idx & 31;
                float va = tempK[(2 * kh) * 65 + e];
                float vb = tempK[(2 * kh + 1) * 65 + e];
                *(float4*)(smf + OKT + e * 128 + 4 * kh) = make_float4(va, va, vb, vb);
            }
            __syncthreads();

            // ---- phase A: sacc[4k][4 q-pairs] = K . Q^T ----
            ull sacc[4][4];
#pragma unroll
            for (int a = 0; a < 4; a++)
#pragma unroll
                for (int j = 0; j < 4; j++) sacc[a][j] = 0ull;

#pragma unroll 4
            for (int e = 0; e < 64; e++) {
                ulonglong2 kd0 = *(const ulonglong2*)(smf + OKT + e * 128 + 8 * kgA);
                ulonglong2 kd1 = *(const ulonglong2*)(smf + OKT + e * 128 + 8 * kgA + 4);
                ulonglong2 qa = *(const ulonglong2*)(smf + OQT + e * 128 + q0);
                ulonglong2 qb = *(const ulonglong2*)(smf + OQT + e * 128 + q0 + 4);
                sacc[0][0] = fma2(kd0.x, qa.x, sacc[0][0]);
                sacc[0][1] = fma2(kd0.x, qa.y, sacc[0][1]);
                sacc[0][2] = fma2(kd0.x, qb.x, sacc[0][2]);
                sacc[0][3] = fma2(kd0.x, qb.y, sacc[0][3]);
                sacc[1][0] = fma2(kd0.y, qa.x, sacc[1][0]);
                sacc[1][1] = fma2(kd0.y, qa.y, sacc[1][1]);
                sacc[1][2] = fma2(kd0.y, qb.x, sacc[1][2]);
                sacc[1][3] = fma2(kd0.y, qb.y, sacc[1][3]);
                sacc[2][0] = fma2(kd1.x, qa.x, sacc[2][0]);
                sacc[2][1] = fma2(kd1.x, qa.y, sacc[2][1]);
                sacc[2][2] = fma2(kd1.x, qb.x, sacc[2][2]);
                sacc[2][3] = fma2(kd1.x, qb.y, sacc[2][3]);
                sacc[3][0] = fma2(kd1.y, qa.x, sacc[3][0]);
                sacc[3][1] = fma2(kd1.y, qa.y, sacc[3][1]);
                sacc[3][2] = fma2(kd1.y, qb.x, sacc[3][2]);
                sacc[3][3] = fma2(kd1.y, qb.y, sacc[3][3]);
            }
            // exp + store S^T rows 4*kgA..+3, cols q0..q0+7
#pragma unroll
            for (int a = 0; a < 4; a++) {
                float2 s0 = unpack2(sacc[a][0]);
                float2 s1 = unpack2(sacc[a][1]);
                float2 s2 = unpack2(sacc[a][2]);
                float2 s3 = unpack2(sacc[a][3]);
                *(float4*)(smf + OS + (4 * kgA + a) * SPAD + q0) =
                    make_float4(__expf(s0.x), __expf(s0.y), __expf(s1.x), __expf(s1.y));
                *(float4*)(smf + OS + (4 * kgA + a) * SPAD + q0 + 4) =
                    make_float4(__expf(s2.x), __expf(s2.y), __expf(s3.x), __expf(s3.y));
            }
            __syncthreads();

            // ---- phase B: o += S^T . V ; row sums ----
#pragma unroll 4
            for (int k = 0; k < 64; k++) {
                ulonglong2 pa = *(const ulonglong2*)(smf + OS + k * SPAD + q0);
                ulonglong2 pb = *(const ulonglong2*)(smf + OS + k * SPAD + q0 + 4);
                ulonglong2 vd0 = *(const ulonglong2*)(smf + OV + k * 128 + 8 * egB);
                ulonglong2 vd1 = *(const ulonglong2*)(smf + OV + k * 128 + 8 * egB + 4);
                o[0][0] = fma2(pa.x, vd0.x, o[0][0]);
                o[0][1] = fma2(pa.x, vd0.y, o[0][1]);
                o[0][2] = fma2(pa.x, vd1.x, o[0][2]);
                o[0][3] = fma2(pa.x, vd1.y, o[0][3]);
                o[1][0] = fma2(pa.y, vd0.x, o[1][0]);
                o[1][1] = fma2(pa.y, vd0.y, o[1][1]);
                o[1][2] = fma2(pa.y, vd1.x, o[1][2]);
                o[1][3] = fma2(pa.y, vd1.y, o[1][3]);
                o[2][0] = fma2(pb.x, vd0.x, o[2][0]);
                o[2][1] = fma2(pb.x, vd0.y, o[2][1]);
                o[2][2] = fma2(pb.x, vd1.x, o[2][2]);
                o[2][3] = fma2(pb.x, vd1.y, o[2][3]);
                o[3][0] = fma2(pb.y, vd0.x, o[3][0]);
                o[3][1] = fma2(pb.y, vd0.y, o[3][1]);
                o[3][2] = fma2(pb.y, vd1.x, o[3][2]);
                o[3][3] = fma2(pb.y, vd1.y, o[3][3]);
                sa[0] = add2(sa[0], pa.x);
                sa[1] = add2(sa[1], pa.y);
                sa[2] = add2(sa[2], pb.x);
                sa[3] = add2(sa[3], pb.y);
            }
            __syncthreads();
        }

        // ---- ssum publish ----
        if (egB == 0) {
#pragma unroll
            for (int j = 0; j < 4; j++) {
                float2 f = unpack2(sa[j]);
                smf[OSUM + q0 + 2 * j] = f.x;
                smf[OSUM + q0 + 2 * j + 1] = f.y;
            }
        }
        __syncthreads();

        // ---- wait for this (b,h)'s inter results (long since done) ----
        if (t == 0) {
            volatile int* f = g_flag + bh;
            while (*f == 0) {}
        }
        __syncthreads();
        __threadfence();   // acquire before reading g_Vinter

        // ---- normalize + fused broadcast store ----
        const int e0B = egB * 4;
        float inv[8];
#pragma unroll
        for (int j = 0; j < 8; j++) inv[j] = 1.0f / smf[OSUM + q0 + j];
#pragma unroll
        for (int qp = 0; qp < 4; qp++) {
            ull ip = pack2(inv[2 * qp], inv[2 * qp + 1]);
#pragma unroll
            for (int j = 0; j < 4; j++) o[qp][j] = mul2(o[qp][j], ip);
        }

        // out rows l = 32q + j (j=0..31); inter row index = q>>2
#pragma unroll
        for (int qp = 0; qp < 4; qp++) {
            int q = q0 + 2 * qp;                 // even; q and q+1 share q>>2
            float2 f0 = unpack2(o[qp][0]);
            float2 f1 = unpack2(o[qp][1]);
            float2 f2 = unpack2(o[qp][2]);
            float2 f3 = unpack2(o[qp][3]);
            float4 iv4 = *(const float4*)(g_Vinter +
                ((size_t)(b * PN + (q >> 2)) * NH + h) * NE + e0B);
            float4 wlo = make_float4(f0.x + iv4.x, f1.x + iv4.y, f2.x + iv4.z, f3.x + iv4.w);
            float4 whi = make_float4(f0.y + iv4.x, f1.y + iv4.y, f2.y + iv4.z, f3.y + iv4.w);
            float* op0 = out + (((size_t)b * 4096 + (size_t)32 * q) * NH + h) * NE + e0B;
            float* op1 = op0 + 32 * 512;         // rows for q+1
#pragma unroll 8
            for (int j = 0; j < 32; j++) {
                *(float4*)(op0 + j * 512) = wlo;
                *(float4*)(op1 + j * 512) = whi;
            }
        }
    }
}

extern "C" void kernel_launch(void* const* d_in, const int* in_sizes, int n_in,
                              void* d_out, int out_size) {
    const float* q_inter = (const float*)d_in[0];
    const float* k_inter = (const float*)d_in[1];
    const float* v_inter = (const float*)d_in[2];
    const float* q_intra = (const float*)d_in[3];
    const float* k_intra = (const float*)d_in[4];
    const float* v_intra = (const float*)d_in[5];
    float* out = (float*)d_out;

    cudaFuncSetAttribute(attn_kernel, cudaFuncAttributeMaxDynamicSharedMemorySize,
                         SMEMF * 4);

    attn_kernel<<<256, 256, SMEMF * 4>>>(q_inter, k_inter, v_inter,
                                         q_intra, k_intra, v_intra, out);
}

// round 11
// speedup vs baseline: 1.0651x; 1.0651x over previous
#include <cuda_runtime.h>

#define NB 16
#define PN 32
#define PS 128
#define NH 8
#define NE 64
// out: [NB, 4096, NH, NE] fp32

typedef unsigned long long ull;

__device__ float g_Vintra[NB * PS * NH * NE];   // 4 MB (normalized)
__device__ float g_Vinter[NB * PN * NH * NE];   // 1 MB (normalized)

// Packed f32x2 ops — operands stay in aligned register pairs.
__device__ __forceinline__ ull fma2(ull a, ull b, ull c) {
    ull d; asm("fma.rn.f32x2 %0, %1, %2, %3;" : "=l"(d) : "l"(a), "l"(b), "l"(c)); return d;
}
__device__ __forceinline__ ull mul2(ull a, ull b) {
    ull d; asm("mul.rn.f32x2 %0, %1, %2;" : "=l"(d) : "l"(a), "l"(b)); return d;
}
__device__ __forceinline__ ull add2(ull a, ull b) {
    ull d; asm("add.rn.f32x2 %0, %1, %2;" : "=l"(d) : "l"(a), "l"(b)); return d;
}
__device__ __forceinline__ ull pack2(float lo, float hi) {
    ull r; asm("mov.b64 %0, {%1, %2};" : "=l"(r) : "f"(lo), "f"(hi)); return r;
}
__device__ __forceinline__ float2 unpack2(ull v) {
    float2 f; asm("mov.b64 {%0, %1}, %2;" : "=f"(f.x), "=f"(f.y) : "l"(v)); return f;
}

// ---- dynamic smem layout (float offsets), intra path ----
// K^T and V stored PRE-DUPLICATED ({x,x} pairs): inner loops are pure
// LDS.128 -> fma.rn.f32x2, no register pack MOVs.
#define OQT   0        // Q^T      [64e][128q]          8192 floats
#define OKT   8192     // K^T dup  [64e][128(2k)]       8192
#define OV    16384    // V dup    [64k][128(2e)]       8192
#define OS    24576    // S^T [64k][SPAD]=8448; also bounce temp
#define OSUM  33024    // intra ssum [128]
#define SMEMF 33152    // 132608 bytes -> 1 CTA/SM, but now 16 warps resident
#define SPAD  132

extern __shared__ float smf[];

// grid = 256 x 512 threads (16 warps/SM, 1 CTA/SM):
//   blk < 128:  intra (b,h): 128q x 128k two-phase GEMM, staged ONCE,
//               work split across 512 threads. -> g_Vintra.
//   blk >= 128: inter (b,h): 32q x 32k over 512 threads. -> g_Vinter.
// Single-pass softmax without max-subtraction: scores q.k/8 with unit-normal
// inputs are bounded (|s| < ~7) so exp cannot overflow; mathematically
// identical to reference softmax up to fp32 add order.
__global__ __launch_bounds__(512) void attn_kernel(
    const float* __restrict__ q_inter, const float* __restrict__ k_inter,
    const float* __restrict__ v_inter,
    const float* __restrict__ q_intra, const float* __restrict__ k_intra,
    const float* __restrict__ v_intra)
{
    const int blk = blockIdx.x;
    const int t = threadIdx.x;

    if (blk < 128) {
        // ================= intra: 128q x 128k =================
        const int b = blk >> 3, h = blk & 7;

        // ---- build Q^T (pre-scaled by 1/8) via smem bounce ----
        float* tempQ = smf + OS;   // [128][65]
        {
            const float4* q4 = (const float4*)q_intra;
#pragma unroll
            for (int i = 0; i < 4; i++) {
                int idx = t + i * 512;             // 128 rows x 16 float4
                int q = idx >> 4, e4 = idx & 15;
                float4 v = q4[((b * PS + q) * NH + h) * 16 + e4];
                float* d = tempQ + q * 65 + 4 * e4;
                d[0] = v.x * 0.125f; d[1] = v.y * 0.125f;
                d[2] = v.z * 0.125f; d[3] = v.w * 0.125f;
            }
        }
        __syncthreads();
#pragma unroll
        for (int i = 0; i < 4; i++) {
            int idx = t + i * 512;                 // 64e x 32 q-groups
            int e = idx >> 5, q0 = (idx & 31) * 4;
            float4 w;
            w.x = tempQ[(q0 + 0) * 65 + e];
            w.y = tempQ[(q0 + 1) * 65 + e];
            w.z = tempQ[(q0 + 2) * 65 + e];
            w.w = tempQ[(q0 + 3) * 65 + e];
            *(float4*)(smf + OQT + e * 128 + q0) = w;
        }
        __syncthreads();

        // thread mappings: 512 = 16 qg x 32 (kgA | egB)
        const int qg = t >> 5;         // 0..15 -> queries q0..q0+7
        const int kgA = t & 31;        // phase A: keys 2*kgA, 2*kgA+1
        const int egB = t & 31;        // phase B: elems 2*egB, 2*egB+1
        const int q0 = qg * 8;

        ull o[4][2];                   // [q-pair][e]
        ull sa[4];
#pragma unroll
        for (int a = 0; a < 4; a++) {
            sa[a] = 0ull;
            o[a][0] = 0ull; o[a][1] = 0ull;
        }

        for (int c = 0; c < 2; c++) {
            // ---- stage: K -> bounce tempK; V -> duplicated pairs ----
            float* tempK = smf + OS;   // [64][65]
            {
                const float4* k4 = (const float4*)k_intra;
                const float4* v4 = (const float4*)v_intra;
#pragma unroll
                for (int i = 0; i < 2; i++) {
                    int idx = t + i * 512;         // 64 rows x 16 float4
                    int k = idx >> 4, e4 = idx & 15;
                    int src = ((b * PS + c * 64 + k) * NH + h) * 16 + e4;
                    float4 kv = k4[src];
                    float* d = tempK + k * 65 + 4 * e4;
                    d[0] = kv.x; d[1] = kv.y; d[2] = kv.z; d[3] = kv.w;
                    float4 vv = v4[src];
                    *(float4*)(smf + OV + k * 128 + 8 * e4)     = make_float4(vv.x, vv.x, vv.y, vv.y);
                    *(float4*)(smf + OV + k * 128 + 8 * e4 + 4) = make_float4(vv.z, vv.z, vv.w, vv.w);
                }
            }
            __syncthreads();
            // ---- K^T duplicated transpose: [e][2k] pairs {k,k} ----
#pragma unroll
            for (int i = 0; i < 4; i++) {
                int idx = t + i * 512;             // 64e x 32 key-halves
                int e = idx >> 5, kh = idx & 31;
                float va = tempK[(2 * kh) * 65 + e];
                float vb = tempK[(2 * kh + 1) * 65 + e];
                *(float4*)(smf + OKT + e * 128 + 4 * kh) = make_float4(va, va, vb, vb);
            }
            __syncthreads();

            // ---- phase A: sacc[2k][4 q-pairs] = K . Q^T (pure LDS+FMA2) ----
            ull sacc[2][4];
#pragma unroll
            for (int a = 0; a < 2; a++)
#pragma unroll
                for (int j = 0; j < 4; j++) sacc[a][j] = 0ull;

#pragma unroll 8
            for (int e = 0; e < 64; e++) {
                ulonglong2 kd = *(const ulonglong2*)(smf + OKT + e * 128 + 4 * kgA);
                ulonglong2 qa = *(const ulonglong2*)(smf + OQT + e * 128 + q0);
                ulonglong2 qb = *(const ulonglong2*)(smf + OQT + e * 128 + q0 + 4);
                sacc[0][0] = fma2(kd.x, qa.x, sacc[0][0]);
                sacc[0][1] = fma2(kd.x, qa.y, sacc[0][1]);
                sacc[0][2] = fma2(kd.x, qb.x, sacc[0][2]);
                sacc[0][3] = fma2(kd.x, qb.y, sacc[0][3]);
                sacc[1][0] = fma2(kd.y, qa.x, sacc[1][0]);
                sacc[1][1] = fma2(kd.y, qa.y, sacc[1][1]);
                sacc[1][2] = fma2(kd.y, qb.x, sacc[1][2]);
                sacc[1][3] = fma2(kd.y, qb.y, sacc[1][3]);
            }
            // exp + store S^T rows 2*kgA..+1, cols q0..q0+7
#pragma unroll
            for (int a = 0; a < 2; a++) {
                float2 s0 = unpack2(sacc[a][0]);
                float2 s1 = unpack2(sacc[a][1]);
                float2 s2 = unpack2(sacc[a][2]);
                float2 s3 = unpack2(sacc[a][3]);
                *(float4*)(smf + OS + (2 * kgA + a) * SPAD + q0) =
                    make_float4(__expf(s0.x), __expf(s0.y), __expf(s1.x), __expf(s1.y));
                *(float4*)(smf + OS + (2 * kgA + a) * SPAD + q0 + 4) =
                    make_float4(__expf(s2.x), __expf(s2.y), __expf(s3.x), __expf(s3.y));
            }
            __syncthreads();

            // ---- phase B: o += S^T . V ; row sums ----
#pragma unroll 8
            for (int k = 0; k < 64; k++) {
                ulonglong2 pa = *(const ulonglong2*)(smf + OS + k * SPAD + q0);
                ulonglong2 pb = *(const ulonglong2*)(smf + OS + k * SPAD + q0 + 4);
                ulonglong2 vd = *(const ulonglong2*)(smf + OV + k * 128 + 4 * egB);
                o[0][0] = fma2(pa.x, vd.x, o[0][0]);
                o[0][1] = fma2(pa.x, vd.y, o[0][1]);
                o[1][0] = fma2(pa.y, vd.x, o[1][0]);
                o[1][1] = fma2(pa.y, vd.y, o[1][1]);
                o[2][0] = fma2(pb.x, vd.x, o[2][0]);
                o[2][1] = fma2(pb.x, vd.y, o[2][1]);
                o[3][0] = fma2(pb.y, vd.x, o[3][0]);
                o[3][1] = fma2(pb.y, vd.y, o[3][1]);
                sa[0] = add2(sa[0], pa.x);
                sa[1] = add2(sa[1], pa.y);
                sa[2] = add2(sa[2], pb.x);
                sa[3] = add2(sa[3], pb.y);
            }
            __syncthreads();
        }

        // ---- ssum publish (egB==0: one thread per qg) ----
        if (egB == 0) {
#pragma unroll
            for (int j = 0; j < 4; j++) {
                float2 f = unpack2(sa[j]);
                smf[OSUM + q0 + 2 * j] = f.x;
                smf[OSUM + q0 + 2 * j + 1] = f.y;
            }
        }
        __syncthreads();

        // ---- normalize + write (float2 per q, e = 2*egB) ----
        const int e0 = 2 * egB;
#pragma unroll
        for (int qp = 0; qp < 4; qp++) {
            int q = q0 + 2 * qp;
            float i0 = 1.0f / smf[OSUM + q];
            float i1 = 1.0f / smf[OSUM + q + 1];
            float2 fe0 = unpack2(o[qp][0]);   // e0   for q (x), q+1 (y)
            float2 fe1 = unpack2(o[qp][1]);   // e0+1 for q, q+1
            size_t base0 = ((size_t)(b * PS + q) * NH + h) * NE + e0;
            size_t base1 = ((size_t)(b * PS + q + 1) * NH + h) * NE + e0;
            *(float2*)(g_Vintra + base0) = make_float2(fe0.x * i0, fe1.x * i0);
            *(float2*)(g_Vintra + base1) = make_float2(fe0.y * i1, fe1.y * i1);
        }
    } else {
        // ================= inter: 32q x 32k, 512 threads =================
        const int bh = blk - 128;
        const int b = bh >> 3, h = bh & 7;

        // stage K(0), V(2048), Q(4096); scores at 6144 [32][33]
        {
            const float4* k4 = (const float4*)k_inter;
            const float4* v4 = (const float4*)v_inter;
            const float4* q4 = (const float4*)q_inter;
            int idx = t;                           // 512 = 32 rows x 16 float4
            int j = idx >> 4, e4 = idx & 15;
            int src = ((b * PN + j) * NH + h) * 16 + e4;
            *(float4*)(smf + idx * 4) = k4[src];
            *(float4*)(smf + 2048 + idx * 4) = v4[src];
            float4 qv = q4[src];
            *(float4*)(smf + 4096 + idx * 4) =
                make_float4(qv.x * 0.125f, qv.y * 0.125f, qv.z * 0.125f, qv.w * 0.125f);
        }
        __syncthreads();

        const int qi = t >> 4;       // 0..31
        {
            // phase A: thread (qi, kg) -> scores for keys 2*kg, 2*kg+1
            const int kg = t & 15;
            const ulonglong2* qp = (const ulonglong2*)(smf + 4096) + qi * 16;
            const ulonglong2* kp = (const ulonglong2*)(smf) + kg * 32;
            ull a0 = 0, a1 = 0;
#pragma unroll
            for (int i = 0; i < 16; i++) {
                ulonglong2 qd = qp[i];
                ulonglong2 k0 = kp[i];
                ulonglong2 k1 = kp[16 + i];
                a0 = fma2(qd.x, k0.x, a0); a0 = fma2(qd.y, k0.y, a0);
                a1 = fma2(qd.x, k1.x, a1); a1 = fma2(qd.y, k1.y, a1);
            }
            float2 f0 = unpack2(a0), f1 = unpack2(a1);
            smf[6144 + (2 * kg + 0) * 33 + qi] = __expf(f0.x + f0.y);
            smf[6144 + (2 * kg + 1) * 33 + qi] = __expf(f1.x + f1.y);
        }
        __syncthreads();
        {
            // phase B: thread (qi, eg) -> 4 elems eg*4..+3, normalized
            const int eg = t & 15;
            const ulonglong2* vbase = (const ulonglong2*)(smf + 2048);
            ull ob0 = 0, ob1 = 0;
            float ss = 0.f;
#pragma unroll 8
            for (int k = 0; k < PN; k++) {
                float s = smf[6144 + k * 33 + qi];
                ss += s;
                ull sp = pack2(s, s);
                ulonglong2 v0 = vbase[k * 16 + eg];
                ob0 = fma2(sp, v0.x, ob0);
                ob1 = fma2(sp, v0.y, ob1);
            }
            float iv = 1.0f / ss;
            ull ip = pack2(iv, iv);
            float2 g0 = unpack2(mul2(ob0, ip));
            float2 g1 = unpack2(mul2(ob1, ip));
            float* dst = g_Vinter + ((size_t)(b * PN + qi) * NH + h) * NE + eg * 4;
            *(float4*)(dst) = make_float4(g0.x, g0.y, g1.x, g1.y);
        }
    }
}

// Broadcast + add. One block per (b, l/32) chunk; sum computed once per
// thread, then 16 pure coalesced STG.128. (Proven ~21 us.)
__global__ __launch_bounds__(256) void bcast_kernel(float* __restrict__ out) {
    const int blk = blockIdx.x;
    const int b = blk >> 7;
    const int l32 = blk & 127;

    const int he = threadIdx.x & 127;
    float4 x = ((const float4*)g_Vintra)[((size_t)b * PS + l32) * 128 + he];
    float4 y = ((const float4*)g_Vinter)[((size_t)b * PN + (l32 >> 2)) * 128 + he];
    x.x += y.x; x.y += y.y; x.z += y.z; x.w += y.w;

    float4* dst = (float4*)out + ((size_t)b * 4096 + (size_t)l32 * 32) * 128;
#pragma unroll
    for (int i = threadIdx.x; i < 4096; i += 256) {
        dst[i] = x;
    }
}

extern "C" void kernel_launch(void* const* d_in, const int* in_sizes, int n_in,
                              void* d_out, int out_size) {
    const float* q_inter = (const float*)d_in[0];
    const float* k_inter = (const float*)d_in[1];
    const float* v_inter = (const float*)d_in[2];
    const float* q_intra = (const float*)d_in[3];
    const float* k_intra = (const float*)d_in[4];
    const float* v_intra = (const float*)d_in[5];
    float* out = (float*)d_out;

    cudaFuncSetAttribute(attn_kernel, cudaFuncAttributeMaxDynamicSharedMemorySize,
                         SMEMF * 4);

    attn_kernel<<<256, 512, SMEMF * 4>>>(q_inter, k_inter, v_inter,
                                         q_intra, k_intra, v_intra);
    bcast_kernel<<<2048, 256>>>(out);
}

// round 13
// speedup vs baseline: 1.5055x; 1.4135x over previous
#include <cuda_runtime.h>
#include <cuda_bf16.h>
#include <cstdint>

#define NB 16
#define PN 32
#define PS 128
#define NH 8
#define NE 64
// out: [NB, 4096, NH, NE] fp32

typedef unsigned long long ull;

__device__ float g_Vintra[NB * PS * NH * NE];   // 4 MB (normalized)
__device__ float g_Vinter[NB * PN * NH * NE];   // 1 MB (normalized)

// ---------- intra smem (bytes). bf16, padded rows -> conflict-free ldmatrix ----------
// Q/K: [128 rows][72 elems] (64 used + 8 pad), row stride 144B (bank shift 4)
// V^T: [64 e-rows][136 elems] (128 used + 8 pad), row stride 272B (bank shift 4)
#define OQH 0
#define OQL 18432
#define OKH 36864
#define OKL 55296
#define OVH 73728
#define OVL 91136
#define SMEM_BYTES 108544

__device__ __forceinline__ uint32_t smem_u32(const void* p) {
    uint32_t a;
    asm("{ .reg .u64 t; cvta.to.shared.u64 t, %1; cvt.u32.u64 %0, t; }" : "=r"(a) : "l"(p));
    return a;
}
__device__ __forceinline__ void ldm4(uint32_t* r, uint32_t addr) {
    asm volatile("ldmatrix.sync.aligned.m8n8.x4.shared.b16 {%0,%1,%2,%3}, [%4];"
                 : "=r"(r[0]), "=r"(r[1]), "=r"(r[2]), "=r"(r[3]) : "r"(addr));
}
__device__ __forceinline__ void mma16816(float* d, const uint32_t* a, uint32_t b0, uint32_t b1) {
    asm volatile(
        "mma.sync.aligned.m16n8k16.row.col.f32.bf16.bf16.f32 "
        "{%0,%1,%2,%3}, {%4,%5,%6,%7}, {%8,%9}, {%0,%1,%2,%3};"
        : "+f"(d[0]), "+f"(d[1]), "+f"(d[2]), "+f"(d[3])
        : "r"(a[0]), "r"(a[1]), "r"(a[2]), "r"(a[3]), "r"(b0), "r"(b1));
}
__device__ __forceinline__ uint32_t pack_bf2(__nv_bfloat16 a, __nv_bfloat16 b) {
    __nv_bfloat162 h = __halves2bfloat162(a, b);
    return *reinterpret_cast<uint32_t*>(&h);
}
// split x into bf16 hi + bf16 lo (x ~= hi + lo)
__device__ __forceinline__ void split_bf(float x, __nv_bfloat16& hi, __nv_bfloat16& lo) {
    hi = __float2bfloat16(x);
    lo = __float2bfloat16(x - __bfloat162float(hi));
}

// packed-fp32 helpers for the SIMT inter branch
__device__ __forceinline__ ull fma2(ull a, ull b, ull c) {
    ull d; asm("fma.rn.f32x2 %0, %1, %2, %3;" : "=l"(d) : "l"(a), "l"(b), "l"(c)); return d;
}
__device__ __forceinline__ ull mul2(ull a, ull b) {
    ull d; asm("mul.rn.f32x2 %0, %1, %2;" : "=l"(d) : "l"(a), "l"(b)); return d;
}
__device__ __forceinline__ ull add2(ull a, ull b) {
    ull d; asm("add.rn.f32x2 %0, %1, %2;" : "=l"(d) : "l"(a), "l"(b)); return d;
}
__device__ __forceinline__ ull pack2(float lo, float hi) {
    ull r; asm("mov.b64 %0, {%1, %2};" : "=l"(r) : "f"(lo), "f"(hi)); return r;
}
__device__ __forceinline__ float2 unpack2(ull v) {
    float2 f; asm("mov.b64 {%0, %1}, %2;" : "=f"(f.x), "=f"(f.y) : "l"(v)); return f;
}

extern __shared__ char smc[];

// grid = 256 x 256 threads:
//   blk < 128:  intra (b,h) via warp-level bf16-split HMMA (mma.sync).
//               Warp w owns q-rows [16w,16w+16). Phase A: S = QK^T (3 split
//               products). exp in registers; P repacked to A-fragments in
//               REGISTERS (C-frag layout == A-frag layout). Phase B: O = PV.
//   blk >= 128: inter (b,h) SIMT (32q x 32k, threads 0-31).
// Split-bf16: x = hi + lo; keep hh + hl + lh -> ~1e-4 relative accuracy.
// Softmax without max-subtraction is safe (|score| < ~7, unit-normal inputs);
// row sums are exact fp32.
__global__ __launch_bounds__(256) void attn_kernel(
    const float* __restrict__ q_inter, const float* __restrict__ k_inter,
    const float* __restrict__ v_inter,
    const float* __restrict__ q_intra, const float* __restrict__ k_intra,
    const float* __restrict__ v_intra)
{
    const int blk = blockIdx.x;
    const int t = threadIdx.x;

    if (blk < 128) {
        // ================= intra: HMMA path =================
        const int b = blk >> 3, h = blk & 7;
        const int w = t >> 5, lane = t & 31;
        const int gid = lane >> 2, tg = lane & 3;
        const uint32_t smb = smem_u32(smc);

        // ---- stage Q (x0.125) and K as bf16 hi/lo [128][72] ----
        {
            const float4* q4 = (const float4*)q_intra;
            const float4* k4 = (const float4*)k_intra;
#pragma unroll
            for (int i = 0; i < 8; i++) {
                int idx = t + i * 256;             // 128 rows x 16 float4
                int r = idx >> 4, e4 = idx & 15;
                int src = ((b * PS + r) * NH + h) * 16 + e4;
                uint32_t off = r * 144 + e4 * 8;   // bytes
                {
                    float4 v = q4[src];
                    __nv_bfloat16 h0, l0, h1, l1, h2, l2, h3, l3;
                    split_bf(v.x * 0.125f, h0, l0);
                    split_bf(v.y * 0.125f, h1, l1);
                    split_bf(v.z * 0.125f, h2, l2);
                    split_bf(v.w * 0.125f, h3, l3);
                    *(uint32_t*)(smc + OQH + off)     = pack_bf2(h0, h1);
                    *(uint32_t*)(smc + OQH + off + 4) = pack_bf2(h2, h3);
                    *(uint32_t*)(smc + OQL + off)     = pack_bf2(l0, l1);
                    *(uint32_t*)(smc + OQL + off + 4) = pack_bf2(l2, l3);
                }
                {
                    float4 v = k4[src];
                    __nv_bfloat16 h0, l0, h1, l1, h2, l2, h3, l3;
                    split_bf(v.x, h0, l0);
                    split_bf(v.y, h1, l1);
                    split_bf(v.z, h2, l2);
                    split_bf(v.w, h3, l3);
                    *(uint32_t*)(smc + OKH + off)     = pack_bf2(h0, h1);
                    *(uint32_t*)(smc + OKH + off + 4) = pack_bf2(h2, h3);
                    *(uint32_t*)(smc + OKL + off)     = pack_bf2(l0, l1);
                    *(uint32_t*)(smc + OKL + off + 4) = pack_bf2(l2, l3);
                }
            }
        }
        // ---- stage V^T [64e][136k] hi/lo ----
        {
            const float4* v4 = (const float4*)v_intra;
#pragma unroll
            for (int i = 0; i < 8; i++) {
                int idx = t + i * 256;
                int k = idx >> 4, e4 = idx & 15;
                float4 v = v4[((b * PS + k) * NH + h) * 16 + e4];
                float xs[4] = {v.x, v.y, v.z, v.w};
#pragma unroll
                for (int j = 0; j < 4; j++) {
                    int e = e4 * 4 + j;
                    __nv_bfloat16 hi, lo;
                    split_bf(xs[j], hi, lo);
                    uint32_t off = e * 272 + k * 2;
                    *(__nv_bfloat16*)(smc + OVH + off) = hi;
                    *(__nv_bfloat16*)(smc + OVL + off) = lo;
                }
            }
        }
        __syncthreads();

        // ---- ldmatrix lane addresses ----
        // A-frag (m16k16): row = 16w + (lane&15), col = (lane&16)?8:0
        const uint32_t arow = 16 * w + (lane & 15);
        const uint32_t acol = (lane & 16) ? 8u : 0u;
        const uint32_t aQH = smb + OQH + arow * 144 + acol * 2;
        const uint32_t aQL = smb + OQL + arow * 144 + acol * 2;
        // B-frag pair (2 n-tiles): row = (lane&7) + ((lane&16)?8:0), col = (lane&8)?8:0
        const uint32_t brow = (lane & 7) + ((lane & 16) ? 8u : 0u);
        const uint32_t bcol = (lane & 8) ? 8u : 0u;
        const uint32_t bKH = smb + OKH + brow * 144 + bcol * 2;
        const uint32_t bKL = smb + OKL + brow * 144 + bcol * 2;
        const uint32_t bVH = smb + OVH + brow * 272 + bcol * 2;
        const uint32_t bVL = smb + OVL + brow * 272 + bcol * 2;

        // ---- phase A: S[16q][128k], 16 n-tiles x 4 f32 regs ----
        float sacc[16][4];
#pragma unroll
        for (int n = 0; n < 16; n++)
#pragma unroll
            for (int j = 0; j < 4; j++) sacc[n][j] = 0.f;

#pragma unroll
        for (int s = 0; s < 4; s++) {                 // k-dim (e) steps of 16
            uint32_t ah[4], al[4];
            ldm4(ah, aQH + s * 32);
            ldm4(al, aQL + s * 32);
#pragma unroll
            for (int p = 0; p < 8; p++) {             // n-tile pairs (16 k-rows)
                uint32_t bh[4], bl[4];
                ldm4(bh, bKH + p * 2304 + s * 32);    // 2304 = 16 rows * 144B
                ldm4(bl, bKL + p * 2304 + s * 32);
                mma16816(sacc[2 * p],     ah, bh[0], bh[1]);
                mma16816(sacc[2 * p],     al, bh[0], bh[1]);
                mma16816(sacc[2 * p],     ah, bl[0], bl[1]);
                mma16816(sacc[2 * p + 1], ah, bh[2], bh[3]);
                mma16816(sacc[2 * p + 1], al, bh[2], bh[3]);
                mma16816(sacc[2 * p + 1], ah, bl[2], bl[3]);
            }
        }

        // ---- softmax in registers; row sums via 2 shfl ----
        float rs0 = 0.f, rs1 = 0.f;
#pragma unroll
        for (int n = 0; n < 16; n++) {
            sacc[n][0] = __expf(sacc[n][0]);
            sacc[n][1] = __expf(sacc[n][1]);
            sacc[n][2] = __expf(sacc[n][2]);
            sacc[n][3] = __expf(sacc[n][3]);
            rs0 += sacc[n][0] + sacc[n][1];
            rs1 += sacc[n][2] + sacc[n][3];
        }
        rs0 += __shfl_xor_sync(0xffffffffu, rs0, 1);
        rs0 += __shfl_xor_sync(0xffffffffu, rs0, 2);
        rs1 += __shfl_xor_sync(0xffffffffu, rs1, 1);
        rs1 += __shfl_xor_sync(0xffffffffu, rs1, 2);

        // ---- phase B: O[16q][64e] = P.V, P rebuilt in registers ----
        float oacc[8][4];
#pragma unroll
        for (int n = 0; n < 8; n++)
#pragma unroll
            for (int j = 0; j < 4; j++) oacc[n][j] = 0.f;

#pragma unroll
        for (int s = 0; s < 8; s++) {                 // k-dim (key) steps of 16
            // A-frag from C-frags of n-tiles 2s, 2s+1 (identical layouts)
            uint32_t ah[4], al[4];
            {
                __nv_bfloat16 h0, l0, h1, l1;
                split_bf(sacc[2 * s][0], h0, l0); split_bf(sacc[2 * s][1], h1, l1);
                ah[0] = pack_bf2(h0, h1); al[0] = pack_bf2(l0, l1);
                split_bf(sacc[2 * s][2], h0, l0); split_bf(sacc[2 * s][3], h1, l1);
                ah[1] = pack_bf2(h0, h1); al[1] = pack_bf2(l0, l1);
                split_bf(sacc[2 * s + 1][0], h0, l0); split_bf(sacc[2 * s + 1][1], h1, l1);
                ah[2] = pack_bf2(h0, h1); al[2] = pack_bf2(l0, l1);
                split_bf(sacc[2 * s + 1][2], h0, l0); split_bf(sacc[2 * s + 1][3], h1, l1);
                ah[3] = pack_bf2(h0, h1); al[3] = pack_bf2(l0, l1);
            }
#pragma unroll
            for (int ep = 0; ep < 4; ep++) {          // e-tile pairs (16 e-rows)
                uint32_t vh[4], vl[4];
                ldm4(vh, bVH + ep * 4352 + s * 32);   // 4352 = 16 rows * 272B
                ldm4(vl, bVL + ep * 4352 + s * 32);
                mma16816(oacc[2 * ep],     ah, vh[0], vh[1]);
                mma16816(oacc[2 * ep],     al, vh[0], vh[1]);
                mma16816(oacc[2 * ep],     ah, vl[0], vl[1]);
                mma16816(oacc[2 * ep + 1], ah, vh[2], vh[3]);
                mma16816(oacc[2 * ep + 1], al, vh[2], vh[3]);
                mma16816(oacc[2 * ep + 1], ah, vl[2], vl[3]);
            }
        }

        // ---- normalize + write ----
        {
            float inv0 = 1.0f / rs0;
            float inv1 = 1.0f / rs1;
            int q0r = 16 * w + gid;
            float* d0 = g_Vintra + ((size_t)(b * PS + q0r) * NH + h) * NE;
            float* d1 = g_Vintra + ((size_t)(b * PS + q0r + 8) * NH + h) * NE;
#pragma unroll
            for (int n = 0; n < 8; n++) {
                int e = n * 8 + tg * 2;
                *(float2*)(d0 + e) = make_float2(oacc[n][0] * inv0, oacc[n][1] * inv0);
                *(float2*)(d1 + e) = make_float2(oacc[n][2] * inv1, oacc[n][3] * inv1);
            }
        }
    } else {
        // ================= inter: SIMT 32q x 32k =================
        const int bh = blk - 128;
        const int b = bh >> 3, h = bh & 7;
        float* smf = (float*)smc;
        ulonglong2* sK = (ulonglong2*)smf;
        ulonglong2* sV = (ulonglong2*)(smf + PN * NE);

        const float4* k4 = (const float4*)k_inter;
        const float4* v4 = (const float4*)v_inter;
        for (int i = t; i < PN * 16; i += 256) {
            int j = i >> 4, e4 = i & 15;
            int src = ((b * PN + j) * NH + h) * 16 + e4;
            ((float4*)sK)[i] = k4[src];
            ((float4*)sV)[i] = v4[src];
        }
        __syncthreads();

        if (t < PN) {
            ull q2[32];
            {
                const float4* qq = (const float4*)(q_inter + ((size_t)(b * PN + t) * NH + h) * NE);
#pragma unroll
                for (int i = 0; i < 16; i++) {
                    float4 v = qq[i];
                    q2[2 * i]     = pack2(v.x * 0.125f, v.y * 0.125f);
                    q2[2 * i + 1] = pack2(v.z * 0.125f, v.w * 0.125f);
                }
            }
            ull o2[32];
#pragma unroll
            for (int i = 0; i < 32; i++) o2[i] = 0ull;
            float ssum = 0.f;

            for (int j = 0; j < PN; j++) {
                const ulonglong2* kr = sK + j * 16;
                ulonglong2 k0 = kr[0], k1 = kr[1];
                ull a0 = mul2(q2[0], k0.x);
                ull a1 = mul2(q2[1], k0.y);
                ull a2 = mul2(q2[2], k1.x);
                ull a3 = mul2(q2[3], k1.y);
#pragma unroll
                for (int i = 2; i < 16; i += 2) {
                    ulonglong2 ka = kr[i], kb = kr[i + 1];
                    a0 = fma2(q2[2 * i],     ka.x, a0);
                    a1 = fma2(q2[2 * i + 1], ka.y, a1);
                    a2 = fma2(q2[2 * i + 2], kb.x, a2);
                    a3 = fma2(q2[2 * i + 3], kb.y, a3);
                }
                a0 = add2(a0, a1);
                a2 = add2(a2, a3);
                a0 = add2(a0, a2);
                float2 f = unpack2(a0);
                float p = __expf(f.x + f.y);
                ssum += p;
                ull pp = pack2(p, p);
                const ulonglong2* vr = sV + j * 16;
#pragma unroll
                for (int i = 0; i < 16; i++) {
                    ulonglong2 vv = vr[i];
                    o2[2 * i]     = fma2(pp, vv.x, o2[2 * i]);
                    o2[2 * i + 1] = fma2(pp, vv.y, o2[2 * i + 1]);
                }
            }

            float iv = 1.0f / ssum;
            ull ii = pack2(iv, iv);
            float4* dst = (float4*)(g_Vinter + ((size_t)(b * PN + t) * NH + h) * NE);
#pragma unroll
            for (int i = 0; i < 16; i++) {
                float2 lo = unpack2(mul2(o2[2 * i], ii));
                float2 hi = unpack2(mul2(o2[2 * i + 1], ii));
                dst[i] = make_float4(lo.x, lo.y, hi.x, hi.y);
            }
        }
    }
}

// Broadcast + add (proven ~20.7 us, ~81% of HBM write spec).
__global__ __launch_bounds__(256) void bcast_kernel(float* __restrict__ out) {
    const int blk = blockIdx.x;
    const int b = blk >> 7;
    const int l32 = blk & 127;

    const int he = threadIdx.x & 127;
    float4 x = ((const float4*)g_Vintra)[((size_t)b * PS + l32) * 128 + he];
    float4 y = ((const float4*)g_Vinter)[((size_t)b * PN + (l32 >> 2)) * 128 + he];
    x.x += y.x; x.y += y.y; x.z += y.z; x.w += y.w;

    float4* dst = (float4*)out + ((size_t)b * 4096 + (size_t)l32 * 32) * 128;
#pragma unroll
    for (int i = threadIdx.x; i < 4096; i += 256) {
        dst[i] = x;
    }
}

extern "C" void kernel_launch(void* const* d_in, const int* in_sizes, int n_in,
                              void* d_out, int out_size) {
    const float* q_inter = (const float*)d_in[0];
    const float* k_inter = (const float*)d_in[1];
    const float* v_inter = (const float*)d_in[2];
    const float* q_intra = (const float*)d_in[3];
    const float* k_intra = (const float*)d_in[4];
    const float* v_intra = (const float*)d_in[5];
    float* out = (float*)d_out;

    cudaFuncSetAttribute(attn_kernel, cudaFuncAttributeMaxDynamicSharedMemorySize,
                         SMEM_BYTES);

    attn_kernel<<<256, 256, SMEM_BYTES>>>(q_inter, k_inter, v_inter,
                                          q_intra, k_intra, v_intra);
    bcast_kernel<<<2048, 256>>>(out);
}